// round 5
// baseline (speedup 1.0000x reference)
#include <cuda_runtime.h>
#include <math.h>

// Problem constants: B=2, H=16, S=2048, D=64
#define Bn    2
#define Hn    16
#define Sn    2048
#define Dn    64
#define BM    128
#define BN    128
#define NTHR  256
#define LDQ   132        // Q^T / K^T smem row stride (floats)
#define LDV   68         // V smem row stride (floats)
#define NEGF  (-3.402823466e38f)

// smem layout (floats)
#define QS_OFF 0
#define KS_OFF (Dn * LDQ)                 // 8448
#define VS_OFF (KS_OFF + Dn * LDQ)        // 16896
#define PS_OFF (VS_OFF + BN * LDV)        // 25600
#define SMEM_FLOATS (PS_OFF + BN * 128)   // 41984
#define SMEM_BYTES  (SMEM_FLOATS * 4)     // 167936 B

// mask dtype mode: 0 = uint8 bytes, 1 = int32 0/1, 2 = float32 0.0/1.0
__device__ int g_mask_mode;

__global__ void probe_mask_kernel(const unsigned int* __restrict__ m)
{
    __shared__ int s_i32ok, s_f32ok;
    if (threadIdx.x == 0) { s_i32ok = 1; s_f32ok = 1; }
    __syncthreads();
    int i32ok = 1, f32ok = 1;
    for (int i = threadIdx.x; i < 16384; i += blockDim.x) {
        unsigned int w = m[i];
        if (w > 1u)                      i32ok = 0;
        if (w != 0u && w != 0x3F800000u) f32ok = 0;
    }
    if (!i32ok) atomicAnd(&s_i32ok, 0);
    if (!f32ok) atomicAnd(&s_f32ok, 0);
    __syncthreads();
    if (threadIdx.x == 0)
        g_mask_mode = s_i32ok ? 1 : (s_f32ok ? 2 : 0);
}

__global__ __launch_bounds__(NTHR, 1)
void attn_fp32_kernel(const float* __restrict__ Q,
                      const float* __restrict__ K,
                      const float* __restrict__ V,
                      const void* __restrict__ Mraw,
                      float* __restrict__ O)
{
    extern __shared__ float sm[];
    float* Qs = sm + QS_OFF;   // [Dn][LDQ]   Q^T
    float* Ks = sm + KS_OFF;   // [Dn][LDQ]   K^T
    float* Vs = sm + VS_OFF;   // [BN][LDV]   V natural
    float* Ps = sm + PS_OFF;   // [BN][128]   P^T, rotated-block swizzle

    const int bh  = blockIdx.y;      // b*H + h
    const int b   = bh >> 4;         // H = 16
    const int q0  = blockIdx.x * BM;
    const int tid = threadIdx.x;
    const int tx  = tid & 15;
    const int ty  = tid >> 4;
    const int mode = g_mask_mode;

    const float* Qg = Q + (size_t)bh * Sn * Dn;
    const float* Kg = K + (size_t)bh * Sn * Dn;
    const float* Vg = V + (size_t)bh * Sn * Dn;
    float* Og = O + (size_t)bh * Sn * Dn;

    const unsigned char* M8  = (const unsigned char*)Mraw + (size_t)b * Sn * Sn;
    const int*           M32 = (const int*)Mraw           + (size_t)b * Sn * Sn;
    const float*         Mf  = (const float*)Mraw         + (size_t)b * Sn * Sn;

    // ---- load Q tile transposed: Qs[d][r], r in 0..127 ----
    {
        const int r  = tid >> 1;            // 0..127
        const int dc = (tid & 1) * 32;      // 0 or 32
        const float* src = Qg + (size_t)(q0 + r) * Dn + dc;
#pragma unroll
        for (int i = 0; i < 8; i++) {
            float4 v = *(const float4*)(src + i * 4);
            Qs[(dc + 4 * i + 0) * LDQ + r] = v.x;
            Qs[(dc + 4 * i + 1) * LDQ + r] = v.y;
            Qs[(dc + 4 * i + 2) * LDQ + r] = v.z;
            Qs[(dc + 4 * i + 3) * LDQ + r] = v.w;
        }
    }

    float mrow[8], lrow[8], o[8][4];
#pragma unroll
    for (int i = 0; i < 8; i++) {
        mrow[i] = -INFINITY;
        lrow[i] = 0.f;
#pragma unroll
        for (int j = 0; j < 4; j++) o[i][j] = 0.f;
    }

    for (int kt = 0; kt < Sn; kt += BN) {
        // ---- load K tile transposed + V tile natural ----
        {
            const int c  = tid >> 1;
            const int dc = (tid & 1) * 32;
            const float* ksrc = Kg + (size_t)(kt + c) * Dn + dc;
            const float* vsrc = Vg + (size_t)(kt + c) * Dn + dc;
#pragma unroll
            for (int i = 0; i < 8; i++) {
                float4 kv = *(const float4*)(ksrc + i * 4);
                Ks[(dc + 4 * i + 0) * LDQ + c] = kv.x;
                Ks[(dc + 4 * i + 1) * LDQ + c] = kv.y;
                Ks[(dc + 4 * i + 2) * LDQ + c] = kv.z;
                Ks[(dc + 4 * i + 3) * LDQ + c] = kv.w;
                float4 vv = *(const float4*)(vsrc + i * 4);
                *(float4*)(Vs + c * LDV + dc + i * 4) = vv;
            }
        }
        __syncthreads();

        // ---- GEMM1: S = Q K^T, 8x8 fragment (rows ty*4, 64+ty*4; cols tx*4, 64+tx*4) ----
        float s[8][8];
#pragma unroll
        for (int i = 0; i < 8; i++)
#pragma unroll
            for (int j = 0; j < 8; j++) s[i][j] = 0.f;

#pragma unroll 8
        for (int d = 0; d < Dn; d++) {
            const float4 qa = *(const float4*)(Qs + d * LDQ + 4 * ty);
            const float4 qb = *(const float4*)(Qs + d * LDQ + 64 + 4 * ty);
            const float4 ka = *(const float4*)(Ks + d * LDQ + 4 * tx);
            const float4 kb = *(const float4*)(Ks + d * LDQ + 64 + 4 * tx);
            const float qr[8] = {qa.x, qa.y, qa.z, qa.w, qb.x, qb.y, qb.z, qb.w};
            const float kr[8] = {ka.x, ka.y, ka.z, ka.w, kb.x, kb.y, kb.z, kb.w};
#pragma unroll
            for (int i = 0; i < 8; i++)
#pragma unroll
                for (int j = 0; j < 8; j++) s[i][j] += qr[i] * kr[j];
        }

        // ---- mask (BEFORE scaling) then scale ----
#pragma unroll
        for (int i = 0; i < 8; i++) {
            const int ri = (i < 4) ? (4 * ty + i) : (64 + 4 * ty + i - 4);
            const size_t base = (size_t)(q0 + ri) * Sn + kt;
            if (mode == 1) {
                int4 m0 = *(const int4*)(M32 + base + 4 * tx);
                int4 m1 = *(const int4*)(M32 + base + 64 + 4 * tx);
                if (m0.x) s[i][0] = NEGF;  if (m0.y) s[i][1] = NEGF;
                if (m0.z) s[i][2] = NEGF;  if (m0.w) s[i][3] = NEGF;
                if (m1.x) s[i][4] = NEGF;  if (m1.y) s[i][5] = NEGF;
                if (m1.z) s[i][6] = NEGF;  if (m1.w) s[i][7] = NEGF;
            } else if (mode == 0) {
                uchar4 m0 = *(const uchar4*)(M8 + base + 4 * tx);
                uchar4 m1 = *(const uchar4*)(M8 + base + 64 + 4 * tx);
                if (m0.x) s[i][0] = NEGF;  if (m0.y) s[i][1] = NEGF;
                if (m0.z) s[i][2] = NEGF;  if (m0.w) s[i][3] = NEGF;
                if (m1.x) s[i][4] = NEGF;  if (m1.y) s[i][5] = NEGF;
                if (m1.z) s[i][6] = NEGF;  if (m1.w) s[i][7] = NEGF;
            } else {
                float4 m0 = *(const float4*)(Mf + base + 4 * tx);
                float4 m1 = *(const float4*)(Mf + base + 64 + 4 * tx);
                if (m0.x != 0.f) s[i][0] = NEGF;  if (m0.y != 0.f) s[i][1] = NEGF;
                if (m0.z != 0.f) s[i][2] = NEGF;  if (m0.w != 0.f) s[i][3] = NEGF;
                if (m1.x != 0.f) s[i][4] = NEGF;  if (m1.y != 0.f) s[i][5] = NEGF;
                if (m1.z != 0.f) s[i][6] = NEGF;  if (m1.w != 0.f) s[i][7] = NEGF;
            }
#pragma unroll
            for (int j = 0; j < 8; j++) s[i][j] *= 0.125f;   // 1/sqrt(64)
        }

        // ---- online softmax (row spread over 16 lanes tx) ----
#pragma unroll
        for (int i = 0; i < 8; i++) {
            float mx = s[i][0];
#pragma unroll
            for (int j = 1; j < 8; j++) mx = fmaxf(mx, s[i][j]);
#pragma unroll
            for (int off = 1; off < 16; off <<= 1)
                mx = fmaxf(mx, __shfl_xor_sync(0xffffffffu, mx, off));
            const float mnew = fmaxf(mrow[i], mx);
            const float corr = __expf(mrow[i] - mnew);   // exp(-inf)=0 first tile
            float psum = 0.f;
#pragma unroll
            for (int j = 0; j < 8; j++) {
                float p = __expf(s[i][j] - mnew);
                s[i][j] = p;
                psum += p;
            }
#pragma unroll
            for (int off = 1; off < 16; off <<= 1)
                psum += __shfl_xor_sync(0xffffffffu, psum, off);
            lrow[i] = lrow[i] * corr + psum;
            mrow[i] = mnew;
#pragma unroll
            for (int j = 0; j < 4; j++) o[i][j] *= corr;
        }

        // ---- store P^T with rotated-block swizzle: phys rblk = (rblk + c/4) & 31 ----
#pragma unroll
        for (int j = 0; j < 8; j++) {
            const int c    = (j < 4) ? (4 * tx + j) : (64 + 4 * tx + j - 4);
            const int cblk = c >> 2;
            const int pb0  = (ty + cblk) & 31;        // logical rblk = ty
            const int pb1  = (ty + 16 + cblk) & 31;   // logical rblk = ty+16
            *(float4*)(Ps + c * 128 + 4 * pb0) =
                make_float4(s[0][j], s[1][j], s[2][j], s[3][j]);
            *(float4*)(Ps + c * 128 + 4 * pb1) =
                make_float4(s[4][j], s[5][j], s[6][j], s[7][j]);
        }
        __syncthreads();

        // ---- GEMM2: O += P V, 8x4 fragment (out cols = 4*tx..4*tx+3) ----
#pragma unroll 4
        for (int c = 0; c < BN; c++) {
            const int cblk = c >> 2;
            const float4 p0 = *(const float4*)(Ps + c * 128 + 4 * ((ty + cblk) & 31));
            const float4 p1 = *(const float4*)(Ps + c * 128 + 4 * ((ty + 16 + cblk) & 31));
            const float4 vv = *(const float4*)(Vs + c * LDV + 4 * tx);
            const float pr[8] = {p0.x, p0.y, p0.z, p0.w, p1.x, p1.y, p1.z, p1.w};
#pragma unroll
            for (int i = 0; i < 8; i++) {
                o[i][0] += pr[i] * vv.x;
                o[i][1] += pr[i] * vv.y;
                o[i][2] += pr[i] * vv.z;
                o[i][3] += pr[i] * vv.w;
            }
        }
        __syncthreads();
    }

    // ---- normalize and write out ----
#pragma unroll
    for (int i = 0; i < 8; i++) {
        const int ri = (i < 4) ? (4 * ty + i) : (64 + 4 * ty + i - 4);
        const float inv = 1.f / lrow[i];
        float4 r = make_float4(o[i][0] * inv, o[i][1] * inv,
                               o[i][2] * inv, o[i][3] * inv);
        *(float4*)(Og + (size_t)(q0 + ri) * Dn + 4 * tx) = r;
    }
}

extern "C" void kernel_launch(void* const* d_in, const int* in_sizes, int n_in,
                              void* d_out, int out_size)
{
    const float* Q = (const float*)d_in[0];
    const float* K = (const float*)d_in[1];
    const float* V = (const float*)d_in[2];
    const void*  M = (const void*)d_in[3];
    float* O = (float*)d_out;

    cudaFuncSetAttribute(attn_fp32_kernel,
                         cudaFuncAttributeMaxDynamicSharedMemorySize, SMEM_BYTES);

    probe_mask_kernel<<<1, 256>>>((const unsigned int*)M);

    dim3 grid(Sn / BM, Bn * Hn);   // (16, 32)
    attn_fp32_kernel<<<grid, NTHR, SMEM_BYTES>>>(Q, K, V, M, O);
}

// round 6
// speedup vs baseline: 1.9499x; 1.9499x over previous
#include <cuda_runtime.h>
#include <cuda_fp16.h>
#include <math.h>

// Problem constants: B=2, H=16, S=2048, D=64
#define Bn   2
#define Hn   16
#define Sn   2048
#define Dn   64
#define BM   128
#define BN   64
#define NTHR 256
#define NEGF (-3.402823466e38f)

#define LDQ  68      // Q staging row stride (floats)
#define LDK  68      // K tile row stride (floats), natural [key][d]
#define LDVH 80      // V tile row stride (halves), [d][key-permuted]
#define VS_F 4352    // float offset of Vs within smem union
#define SMEM_BYTES 34816   // max(Q stage 128*68*4, Ks 64*68*4 + Vs 64*80*2)

// mask dtype mode: 0 = uint8 bytes, 1 = int32 0/1, 2 = float32 0.0/1.0
__device__ int g_mask_mode;

__global__ void probe_mask_kernel(const unsigned int* __restrict__ m)
{
    __shared__ int s_i32ok, s_f32ok;
    if (threadIdx.x == 0) { s_i32ok = 1; s_f32ok = 1; }
    __syncthreads();
    int i32ok = 1, f32ok = 1;
    for (int i = threadIdx.x; i < 16384; i += blockDim.x) {
        unsigned int w = m[i];
        if (w > 1u)                      i32ok = 0;
        if (w != 0u && w != 0x3F800000u) f32ok = 0;
    }
    if (!i32ok) atomicAnd(&s_i32ok, 0);
    if (!f32ok) atomicAnd(&s_f32ok, 0);
    __syncthreads();
    if (threadIdx.x == 0)
        g_mask_mode = s_i32ok ? 1 : (s_f32ok ? 2 : 0);
}

__device__ __forceinline__ unsigned f2tf(float x)
{
    unsigned u;
    asm("cvt.rna.tf32.f32 %0, %1;" : "=r"(u) : "f"(x));
    return u;
}

__device__ __forceinline__ void mma_tf32(float* d, const unsigned* a,
                                         unsigned b0, unsigned b1)
{
    asm volatile(
        "mma.sync.aligned.m16n8k8.row.col.f32.tf32.tf32.f32 "
        "{%0,%1,%2,%3}, {%4,%5,%6,%7}, {%8,%9}, {%0,%1,%2,%3};"
        : "+f"(d[0]), "+f"(d[1]), "+f"(d[2]), "+f"(d[3])
        : "r"(a[0]), "r"(a[1]), "r"(a[2]), "r"(a[3]), "r"(b0), "r"(b1));
}

__device__ __forceinline__ void mma_f16(float* d, const unsigned* a,
                                        unsigned b0, unsigned b1)
{
    asm volatile(
        "mma.sync.aligned.m16n8k16.row.col.f32.f16.f16.f32 "
        "{%0,%1,%2,%3}, {%4,%5,%6,%7}, {%8,%9}, {%0,%1,%2,%3};"
        : "+f"(d[0]), "+f"(d[1]), "+f"(d[2]), "+f"(d[3])
        : "r"(a[0]), "r"(a[1]), "r"(a[2]), "r"(a[3]), "r"(b0), "r"(b1));
}

__device__ __forceinline__ unsigned packh2(float x, float y)
{
    __half2 h = __floats2half2_rn(x, y);
    return *reinterpret_cast<unsigned*>(&h);
}

__global__ __launch_bounds__(NTHR, 1)
void attn_mma_kernel(const float* __restrict__ Q,
                     const float* __restrict__ K,
                     const float* __restrict__ V,
                     const void* __restrict__ Mraw,
                     float* __restrict__ O)
{
    extern __shared__ float sm[];
    float*    Qst = sm;                       // staging (overlaps Ks/Vs)
    float*    Ksf = sm;                       // [64 key][LDK] tf32 bits as float mem
    unsigned* Ksu = (unsigned*)sm;
    __half*   Vs  = (__half*)(sm + VS_F);     // [64 d][LDVH] halves, key-permuted

    const int bh   = blockIdx.y;
    const int b    = bh >> 4;
    const int q0   = blockIdx.x * BM;
    const int tid  = threadIdx.x;
    const int warp = tid >> 5;
    const int lane = tid & 31;
    const int g    = lane >> 2;      // row group 0..7
    const int c    = lane & 3;       // col pair  0..3
    const int r0   = warp * 16;
    const int mode = g_mask_mode;

    const float* Qg = Q + (size_t)bh * Sn * Dn;
    const float* Kg = K + (size_t)bh * Sn * Dn;
    const float* Vg = V + (size_t)bh * Sn * Dn;
    float*       Og = O + (size_t)bh * Sn * Dn;

    const unsigned char* M8  = (const unsigned char*)Mraw + (size_t)b * Sn * Sn;
    const int*           M32 = (const int*)Mraw           + (size_t)b * Sn * Sn;
    const float*         Mf  = (const float*)Mraw         + (size_t)b * Sn * Sn;

    const int rowA = q0 + r0 + g;    // global q row of c0/c1
    const int rowB = rowA + 8;       // global q row of c2/c3

    // ---- stage Q tile to smem (natural [r][d]) ----
    {
        const int r  = tid >> 1;
        const int dc = (tid & 1) * 32;
        const float* src = Qg + (size_t)(q0 + r) * Dn + dc;
#pragma unroll
        for (int i = 0; i < 8; i++)
            *(float4*)(Qst + r * LDQ + dc + 4 * i) = *(const float4*)(src + 4 * i);
    }
    __syncthreads();

    // ---- Q A-fragments (tf32), persistent in registers ----
    unsigned qa[8][4];
    {
        const int row = r0 + g;
#pragma unroll
        for (int kf = 0; kf < 8; kf++) {
            const int col = 8 * kf + c;
            qa[kf][0] = f2tf(Qst[row * LDQ + col]);
            qa[kf][1] = f2tf(Qst[(row + 8) * LDQ + col]);
            qa[kf][2] = f2tf(Qst[row * LDQ + col + 4]);
            qa[kf][3] = f2tf(Qst[(row + 8) * LDQ + col + 4]);
        }
    }
    __syncthreads();

    float o[8][4];
#pragma unroll
    for (int i = 0; i < 8; i++)
#pragma unroll
        for (int j = 0; j < 4; j++) o[i][j] = 0.f;
    float mrow0 = -INFINITY, mrow1 = -INFINITY;
    float lrow0 = 0.f, lrow1 = 0.f;

    for (int kt = 0; kt < Sn; kt += BN) {
        // ---- K tile -> smem tf32 (natural [key][d], coalesced) ----
        {
            const int key = tid >> 2;
            const int dc  = (tid & 3) * 16;
            const float* src = Kg + (size_t)(kt + key) * Dn + dc;
#pragma unroll
            for (int i = 0; i < 4; i++) {
                float4 v = *(const float4*)(src + 4 * i);
                uint4 u;
                u.x = f2tf(v.x); u.y = f2tf(v.y); u.z = f2tf(v.z); u.w = f2tf(v.w);
                *(uint4*)(Ksu + key * LDK + dc + 4 * i) = u;
            }
        }
        // ---- V tile -> smem fp16 transposed [d][key-permuted] ----
        {
            const int kp = tid & 31;        // key pair 2kp, 2kp+1
            const int d0 = (tid >> 5) * 8;  // 8 d's
            const float* s0 = Vg + (size_t)(kt + 2 * kp) * Dn + d0;
            const float* s1 = s0 + Dn;
            float4 a0 = *(const float4*)(s0),     a1 = *(const float4*)(s0 + 4);
            float4 b0 = *(const float4*)(s1),     b1 = *(const float4*)(s1 + 4);
            const float r0v[8] = {a0.x,a0.y,a0.z,a0.w,a1.x,a1.y,a1.z,a1.w};
            const float r1v[8] = {b0.x,b0.y,b0.z,b0.w,b1.x,b1.y,b1.z,b1.w};
            const int kgbase = (kp >> 3) * 16;
            const int pb     = 4 * (kp & 3) + 2 * ((kp >> 2) & 1);
#pragma unroll
            for (int i = 0; i < 8; i++) {
                __half2 h = __floats2half2_rn(r0v[i], r1v[i]);
                *(__half2*)(Vs + (d0 + i) * LDVH + kgbase + pb) = h;
            }
        }
        __syncthreads();

        // ---- GEMM1: S = Q K^T (tf32), 8 n-frags of m16n8 ----
        float s[8][4];
#pragma unroll
        for (int n = 0; n < 8; n++) {
            s[n][0] = s[n][1] = s[n][2] = s[n][3] = 0.f;
            const int key = 8 * n + g;
#pragma unroll
            for (int kf = 0; kf < 8; kf++) {
                const unsigned b0 = Ksu[key * LDK + 8 * kf + c];
                const unsigned b1 = Ksu[key * LDK + 8 * kf + c + 4];
                mma_tf32(s[n], qa[kf], b0, b1);
            }
        }

        // ---- mask (BEFORE scale) + scale ----
#pragma unroll
        for (int n = 0; n < 8; n++) {
            const int colb = kt + 8 * n + 2 * c;
            if (mode == 1) {
                int2 ma = *(const int2*)(M32 + (size_t)rowA * Sn + colb);
                int2 mb = *(const int2*)(M32 + (size_t)rowB * Sn + colb);
                if (ma.x) s[n][0] = NEGF;  if (ma.y) s[n][1] = NEGF;
                if (mb.x) s[n][2] = NEGF;  if (mb.y) s[n][3] = NEGF;
            } else if (mode == 0) {
                unsigned short ma = *(const unsigned short*)(M8 + (size_t)rowA * Sn + colb);
                unsigned short mb = *(const unsigned short*)(M8 + (size_t)rowB * Sn + colb);
                if (ma & 0xFF)   s[n][0] = NEGF;  if (ma >> 8) s[n][1] = NEGF;
                if (mb & 0xFF)   s[n][2] = NEGF;  if (mb >> 8) s[n][3] = NEGF;
            } else {
                float2 ma = *(const float2*)(Mf + (size_t)rowA * Sn + colb);
                float2 mb = *(const float2*)(Mf + (size_t)rowB * Sn + colb);
                if (ma.x != 0.f) s[n][0] = NEGF;  if (ma.y != 0.f) s[n][1] = NEGF;
                if (mb.x != 0.f) s[n][2] = NEGF;  if (mb.y != 0.f) s[n][3] = NEGF;
            }
            s[n][0] *= 0.125f; s[n][1] *= 0.125f;
            s[n][2] *= 0.125f; s[n][3] *= 0.125f;
        }

        // ---- online softmax (rows split: c0/c1 -> rowA, c2/c3 -> rowB) ----
        float mt0 = -INFINITY, mt1 = -INFINITY;
#pragma unroll
        for (int n = 0; n < 8; n++) {
            mt0 = fmaxf(mt0, fmaxf(s[n][0], s[n][1]));
            mt1 = fmaxf(mt1, fmaxf(s[n][2], s[n][3]));
        }
        mt0 = fmaxf(mt0, __shfl_xor_sync(0xffffffffu, mt0, 1));
        mt0 = fmaxf(mt0, __shfl_xor_sync(0xffffffffu, mt0, 2));
        mt1 = fmaxf(mt1, __shfl_xor_sync(0xffffffffu, mt1, 1));
        mt1 = fmaxf(mt1, __shfl_xor_sync(0xffffffffu, mt1, 2));

        const float mn0 = fmaxf(mrow0, mt0);
        const float mn1 = fmaxf(mrow1, mt1);
        const float cr0 = __expf(mrow0 - mn0);   // 0 on first tile
        const float cr1 = __expf(mrow1 - mn1);

        float p0 = 0.f, p1 = 0.f;
#pragma unroll
        for (int n = 0; n < 8; n++) {
            s[n][0] = __expf(s[n][0] - mn0);
            s[n][1] = __expf(s[n][1] - mn0);
            s[n][2] = __expf(s[n][2] - mn1);
            s[n][3] = __expf(s[n][3] - mn1);
            p0 += s[n][0] + s[n][1];
            p1 += s[n][2] + s[n][3];
        }
        p0 += __shfl_xor_sync(0xffffffffu, p0, 1);
        p0 += __shfl_xor_sync(0xffffffffu, p0, 2);
        p1 += __shfl_xor_sync(0xffffffffu, p1, 1);
        p1 += __shfl_xor_sync(0xffffffffu, p1, 2);

        lrow0 = lrow0 * cr0 + p0;
        lrow1 = lrow1 * cr1 + p1;
        mrow0 = mn0;  mrow1 = mn1;
#pragma unroll
        for (int n = 0; n < 8; n++) {
            o[n][0] *= cr0; o[n][1] *= cr0;
            o[n][2] *= cr1; o[n][3] *= cr1;
        }

        // ---- GEMM2: O += P V (fp16), P from C-frags in-register ----
#pragma unroll
        for (int kg = 0; kg < 4; kg++) {
            unsigned pa[4];
            pa[0] = packh2(s[2 * kg][0],     s[2 * kg][1]);
            pa[1] = packh2(s[2 * kg][2],     s[2 * kg][3]);
            pa[2] = packh2(s[2 * kg + 1][0], s[2 * kg + 1][1]);
            pa[3] = packh2(s[2 * kg + 1][2], s[2 * kg + 1][3]);
#pragma unroll
            for (int nd = 0; nd < 8; nd++) {
                uint2 bb = *(const uint2*)(Vs + (8 * nd + g) * LDVH + 16 * kg + 4 * c);
                mma_f16(o[nd], pa, bb.x, bb.y);
            }
        }
        __syncthreads();
    }

    // ---- epilogue: normalize + store ----
    const float inv0 = 1.f / lrow0;
    const float inv1 = 1.f / lrow1;
#pragma unroll
    for (int nd = 0; nd < 8; nd++) {
        const int dcol = 8 * nd + 2 * c;
        float2 w0 = make_float2(o[nd][0] * inv0, o[nd][1] * inv0);
        float2 w1 = make_float2(o[nd][2] * inv1, o[nd][3] * inv1);
        *(float2*)(Og + (size_t)rowA * Dn + dcol) = w0;
        *(float2*)(Og + (size_t)rowB * Dn + dcol) = w1;
    }
}

extern "C" void kernel_launch(void* const* d_in, const int* in_sizes, int n_in,
                              void* d_out, int out_size)
{
    const float* Q = (const float*)d_in[0];
    const float* K = (const float*)d_in[1];
    const float* V = (const float*)d_in[2];
    const void*  M = (const void*)d_in[3];
    float* O = (float*)d_out;

    cudaFuncSetAttribute(attn_mma_kernel,
                         cudaFuncAttributeMaxDynamicSharedMemorySize, SMEM_BYTES);

    probe_mask_kernel<<<1, 256>>>((const unsigned int*)M);

    dim3 grid(Sn / BM, Bn * Hn);   // (16, 32)
    attn_mma_kernel<<<grid, NTHR, SMEM_BYTES>>>(Q, K, V, M, O);
}

// round 7
// speedup vs baseline: 2.6207x; 1.3440x over previous
#include <cuda_runtime.h>
#include <cuda_fp16.h>
#include <math.h>

// Problem constants: B=2, H=16, S=2048, D=64
#define Bn   2
#define Hn   16
#define Sn   2048
#define Dn   64
#define BM   128
#define BN   64
#define NT   (Sn / BN)     // 32 tiles
#define NTHR 256
#define NEGF (-3.402823466e38f)
#define SCALE2 0.180336880f   // 0.125 * log2(e)

#define LDQ  68      // Q staging row stride (floats)
#define LDK  68      // K tile row stride (uints), natural [key][d]
#define LDVH 80      // V tile row stride (halves), [d][key-permuted]
#define KS_F 4352    // floats: K stage size (64*68)
#define STAGE_F 6912 // floats per stage: K 4352 + V 2560 (64*80 halves)
#define SMEM_BYTES (2 * STAGE_F * 4)   // 55296; Q staging (34816) overlaps stage 0/1

// mask dtype mode: 0 = uint8 bytes, 1 = int32 0/1, 2 = float32 0.0/1.0
__device__ int g_mask_mode;

__global__ void probe_mask_kernel(const unsigned int* __restrict__ m)
{
    __shared__ int s_i32ok, s_f32ok;
    if (threadIdx.x == 0) { s_i32ok = 1; s_f32ok = 1; }
    __syncthreads();
    int i32ok = 1, f32ok = 1;
    for (int i = threadIdx.x; i < 16384; i += blockDim.x) {
        unsigned int w = m[i];
        if (w > 1u)                      i32ok = 0;
        if (w != 0u && w != 0x3F800000u) f32ok = 0;
    }
    if (!i32ok) atomicAnd(&s_i32ok, 0);
    if (!f32ok) atomicAnd(&s_f32ok, 0);
    __syncthreads();
    if (threadIdx.x == 0)
        g_mask_mode = s_i32ok ? 1 : (s_f32ok ? 2 : 0);
}

__device__ __forceinline__ unsigned f2tf(float x)
{
    unsigned u;
    asm("cvt.rna.tf32.f32 %0, %1;" : "=r"(u) : "f"(x));
    return u;
}

__device__ __forceinline__ void mma_tf32(float* d, const unsigned* a,
                                         unsigned b0, unsigned b1)
{
    asm volatile(
        "mma.sync.aligned.m16n8k8.row.col.f32.tf32.tf32.f32 "
        "{%0,%1,%2,%3}, {%4,%5,%6,%7}, {%8,%9}, {%0,%1,%2,%3};"
        : "+f"(d[0]), "+f"(d[1]), "+f"(d[2]), "+f"(d[3])
        : "r"(a[0]), "r"(a[1]), "r"(a[2]), "r"(a[3]), "r"(b0), "r"(b1));
}

__device__ __forceinline__ void mma_f16(float* d, const unsigned* a,
                                        unsigned b0, unsigned b1)
{
    asm volatile(
        "mma.sync.aligned.m16n8k16.row.col.f32.f16.f16.f32 "
        "{%0,%1,%2,%3}, {%4,%5,%6,%7}, {%8,%9}, {%0,%1,%2,%3};"
        : "+f"(d[0]), "+f"(d[1]), "+f"(d[2]), "+f"(d[3])
        : "r"(a[0]), "r"(a[1]), "r"(a[2]), "r"(a[3]), "r"(b0), "r"(b1));
}

__device__ __forceinline__ unsigned packh2(float x, float y)
{
    __half2 h = __floats2half2_rn(x, y);
    return *reinterpret_cast<unsigned*>(&h);
}

__global__ __launch_bounds__(NTHR, 1)
void attn_mma_kernel(const float* __restrict__ Q,
                     const float* __restrict__ K,
                     const float* __restrict__ V,
                     const void* __restrict__ Mraw,
                     float* __restrict__ O)
{
    extern __shared__ float sm[];
    float* Qst = sm;                      // Q staging (overlaps stages)

    const int bh   = blockIdx.y;
    const int b    = bh >> 4;
    const int q0   = blockIdx.x * BM;
    const int tid  = threadIdx.x;
    const int warp = tid >> 5;
    const int lane = tid & 31;
    const int g    = lane >> 2;      // row group 0..7
    const int c    = lane & 3;       // col pair  0..3
    const int r0   = warp * 16;
    const int mode = g_mask_mode;

    const float* Qg = Q + (size_t)bh * Sn * Dn;
    const float* Kg = K + (size_t)bh * Sn * Dn;
    const float* Vg = V + (size_t)bh * Sn * Dn;
    float*       Og = O + (size_t)bh * Sn * Dn;

    const unsigned char* M8  = (const unsigned char*)Mraw + (size_t)b * Sn * Sn;
    const int*           M32 = (const int*)Mraw           + (size_t)b * Sn * Sn;
    const float*         Mf  = (const float*)Mraw         + (size_t)b * Sn * Sn;

    const int rowA = q0 + r0 + g;    // global q row of c0/c1
    const int rowB = rowA + 8;       // global q row of c2/c3

    // loader thread mappings
    const int kkey = tid >> 2;             // 0..63
    const int kdc  = (tid & 3) * 16;       // 0,16,32,48
    const int vkp  = tid & 31;             // key pair
    const int vd0  = (tid >> 5) * 8;       // 8 d's
    const int vkgbase = (vkp >> 3) * 16;
    const int vpb     = 4 * (vkp & 3) + 2 * ((vkp >> 2) & 1);

    // ---- stage Q tile to smem (natural [r][d]) ----
    {
        const int r  = tid >> 1;
        const int dc = (tid & 1) * 32;
        const float* src = Qg + (size_t)(q0 + r) * Dn + dc;
#pragma unroll
        for (int i = 0; i < 8; i++)
            *(float4*)(Qst + r * LDQ + dc + 4 * i) = *(const float4*)(src + 4 * i);
    }
    __syncthreads();

    // ---- Q A-fragments (tf32), persistent in registers ----
    unsigned qa[8][4];
    {
        const int row = r0 + g;
#pragma unroll
        for (int kf = 0; kf < 8; kf++) {
            const int col = 8 * kf + c;
            qa[kf][0] = f2tf(Qst[row * LDQ + col]);
            qa[kf][1] = f2tf(Qst[(row + 8) * LDQ + col]);
            qa[kf][2] = f2tf(Qst[row * LDQ + col + 4]);
            qa[kf][3] = f2tf(Qst[(row + 8) * LDQ + col + 4]);
        }
    }
    __syncthreads();

    float o[8][4];
#pragma unroll
    for (int i = 0; i < 8; i++)
#pragma unroll
        for (int j = 0; j < 4; j++) o[i][j] = 0.f;
    float mrow0 = -INFINITY, mrow1 = -INFINITY;
    float lrow0 = 0.f, lrow1 = 0.f;

    // staging registers
    float4 kst[4];
    float4 va0, va1, vb0, vb1;

    // ---- preload tile 0 ----
    {
        const float* ksrc = Kg + (size_t)kkey * Dn + kdc;
#pragma unroll
        for (int i = 0; i < 4; i++) kst[i] = *(const float4*)(ksrc + 4 * i);
        const float* s0 = Vg + (size_t)(2 * vkp) * Dn + vd0;
        const float* s1 = s0 + Dn;
        va0 = *(const float4*)(s0);  va1 = *(const float4*)(s0 + 4);
        vb0 = *(const float4*)(s1);  vb1 = *(const float4*)(s1 + 4);
    }
    // ---- store tile 0 into stage 0 ----
    {
        unsigned* Ksu = (unsigned*)(sm);
        __half*   Vs  = (__half*)(sm + KS_F);
#pragma unroll
        for (int i = 0; i < 4; i++) {
            uint4 u;
            u.x = f2tf(kst[i].x); u.y = f2tf(kst[i].y);
            u.z = f2tf(kst[i].z); u.w = f2tf(kst[i].w);
            *(uint4*)(Ksu + kkey * LDK + kdc + 4 * i) = u;
        }
        const float r0v[8] = {va0.x,va0.y,va0.z,va0.w,va1.x,va1.y,va1.z,va1.w};
        const float r1v[8] = {vb0.x,vb0.y,vb0.z,vb0.w,vb1.x,vb1.y,vb1.z,vb1.w};
#pragma unroll
        for (int i = 0; i < 8; i++)
            *(__half2*)(Vs + (vd0 + i) * LDVH + vkgbase + vpb) =
                __floats2half2_rn(r0v[i], r1v[i]);
    }
    __syncthreads();

    for (int t = 0; t < NT; t++) {
        const int kt = t * BN;
        unsigned* Ksu = (unsigned*)(sm + (t & 1) * STAGE_F);
        __half*   Vs  = (__half*)(sm + (t & 1) * STAGE_F + KS_F);

        // ---- prefetch mask for THIS tile (latency hidden under GEMM1) ----
        int2  m32a[8], m32b[8];
        unsigned short m8a[8], m8b[8];
        float2 mfa[8], mfb[8];
        if (mode == 1) {
#pragma unroll
            for (int n = 0; n < 8; n++) {
                const int colb = kt + 8 * n + 2 * c;
                m32a[n] = *(const int2*)(M32 + (size_t)rowA * Sn + colb);
                m32b[n] = *(const int2*)(M32 + (size_t)rowB * Sn + colb);
            }
        } else if (mode == 0) {
#pragma unroll
            for (int n = 0; n < 8; n++) {
                const int colb = kt + 8 * n + 2 * c;
                m8a[n] = *(const unsigned short*)(M8 + (size_t)rowA * Sn + colb);
                m8b[n] = *(const unsigned short*)(M8 + (size_t)rowB * Sn + colb);
            }
        } else {
#pragma unroll
            for (int n = 0; n < 8; n++) {
                const int colb = kt + 8 * n + 2 * c;
                mfa[n] = *(const float2*)(Mf + (size_t)rowA * Sn + colb);
                mfb[n] = *(const float2*)(Mf + (size_t)rowB * Sn + colb);
            }
        }

        // ---- prefetch NEXT tile global -> regs ----
        if (t + 1 < NT) {
            const float* ksrc = Kg + (size_t)(kt + BN + kkey) * Dn + kdc;
#pragma unroll
            for (int i = 0; i < 4; i++) kst[i] = *(const float4*)(ksrc + 4 * i);
            const float* s0 = Vg + (size_t)(kt + BN + 2 * vkp) * Dn + vd0;
            const float* s1 = s0 + Dn;
            va0 = *(const float4*)(s0);  va1 = *(const float4*)(s0 + 4);
            vb0 = *(const float4*)(s1);  vb1 = *(const float4*)(s1 + 4);
        }

        // ---- GEMM1: S = Q K^T (tf32), 8 n-frags of m16n8 ----
        float s[8][4];
#pragma unroll
        for (int n = 0; n < 8; n++) {
            s[n][0] = s[n][1] = s[n][2] = s[n][3] = 0.f;
            const int key = 8 * n + g;
#pragma unroll
            for (int kf = 0; kf < 8; kf++) {
                const unsigned b0 = Ksu[key * LDK + 8 * kf + c];
                const unsigned b1 = Ksu[key * LDK + 8 * kf + c + 4];
                mma_tf32(s[n], qa[kf], b0, b1);
            }
        }

        // ---- apply mask (BEFORE scale) + scale (0.125*log2e folded) ----
        if (mode == 1) {
#pragma unroll
            for (int n = 0; n < 8; n++) {
                if (m32a[n].x) s[n][0] = NEGF;  if (m32a[n].y) s[n][1] = NEGF;
                if (m32b[n].x) s[n][2] = NEGF;  if (m32b[n].y) s[n][3] = NEGF;
            }
        } else if (mode == 0) {
#pragma unroll
            for (int n = 0; n < 8; n++) {
                if (m8a[n] & 0xFF) s[n][0] = NEGF;  if (m8a[n] >> 8) s[n][1] = NEGF;
                if (m8b[n] & 0xFF) s[n][2] = NEGF;  if (m8b[n] >> 8) s[n][3] = NEGF;
            }
        } else {
#pragma unroll
            for (int n = 0; n < 8; n++) {
                if (mfa[n].x != 0.f) s[n][0] = NEGF;  if (mfa[n].y != 0.f) s[n][1] = NEGF;
                if (mfb[n].x != 0.f) s[n][2] = NEGF;  if (mfb[n].y != 0.f) s[n][3] = NEGF;
            }
        }
#pragma unroll
        for (int n = 0; n < 8; n++) {
            s[n][0] *= SCALE2; s[n][1] *= SCALE2;
            s[n][2] *= SCALE2; s[n][3] *= SCALE2;
        }

        // ---- online softmax in log2 domain ----
        float mt0 = -INFINITY, mt1 = -INFINITY;
#pragma unroll
        for (int n = 0; n < 8; n++) {
            mt0 = fmaxf(mt0, fmaxf(s[n][0], s[n][1]));
            mt1 = fmaxf(mt1, fmaxf(s[n][2], s[n][3]));
        }
        mt0 = fmaxf(mt0, __shfl_xor_sync(0xffffffffu, mt0, 1));
        mt0 = fmaxf(mt0, __shfl_xor_sync(0xffffffffu, mt0, 2));
        mt1 = fmaxf(mt1, __shfl_xor_sync(0xffffffffu, mt1, 1));
        mt1 = fmaxf(mt1, __shfl_xor_sync(0xffffffffu, mt1, 2));

        const float mn0 = fmaxf(mrow0, mt0);
        const float mn1 = fmaxf(mrow1, mt1);
        const float cr0 = exp2f(mrow0 - mn0);   // 0 on first tile
        const float cr1 = exp2f(mrow1 - mn1);

        float p0 = 0.f, p1 = 0.f;
#pragma unroll
        for (int n = 0; n < 8; n++) {
            s[n][0] = exp2f(s[n][0] - mn0);
            s[n][1] = exp2f(s[n][1] - mn0);
            s[n][2] = exp2f(s[n][2] - mn1);
            s[n][3] = exp2f(s[n][3] - mn1);
            p0 += s[n][0] + s[n][1];
            p1 += s[n][2] + s[n][3];
        }
        p0 += __shfl_xor_sync(0xffffffffu, p0, 1);
        p0 += __shfl_xor_sync(0xffffffffu, p0, 2);
        p1 += __shfl_xor_sync(0xffffffffu, p1, 1);
        p1 += __shfl_xor_sync(0xffffffffu, p1, 2);

        lrow0 = lrow0 * cr0 + p0;
        lrow1 = lrow1 * cr1 + p1;
        mrow0 = mn0;  mrow1 = mn1;
#pragma unroll
        for (int n = 0; n < 8; n++) {
            o[n][0] *= cr0; o[n][1] *= cr0;
            o[n][2] *= cr1; o[n][3] *= cr1;
        }

        // ---- GEMM2: O += P V (fp16), P from C-frags in-register ----
#pragma unroll
        for (int kg = 0; kg < 4; kg++) {
            unsigned pa[4];
            pa[0] = packh2(s[2 * kg][0],     s[2 * kg][1]);
            pa[1] = packh2(s[2 * kg][2],     s[2 * kg][3]);
            pa[2] = packh2(s[2 * kg + 1][0], s[2 * kg + 1][1]);
            pa[3] = packh2(s[2 * kg + 1][2], s[2 * kg + 1][3]);
#pragma unroll
            for (int nd = 0; nd < 8; nd++) {
                uint2 bb = *(const uint2*)(Vs + (8 * nd + g) * LDVH + 16 * kg + 4 * c);
                mma_f16(o[nd], pa, bb.x, bb.y);
            }
        }

        // ---- store prefetched NEXT tile into other stage ----
        if (t + 1 < NT) {
            unsigned* Ksu2 = (unsigned*)(sm + ((t + 1) & 1) * STAGE_F);
            __half*   Vs2  = (__half*)(sm + ((t + 1) & 1) * STAGE_F + KS_F);
#pragma unroll
            for (int i = 0; i < 4; i++) {
                uint4 u;
                u.x = f2tf(kst[i].x); u.y = f2tf(kst[i].y);
                u.z = f2tf(kst[i].z); u.w = f2tf(kst[i].w);
                *(uint4*)(Ksu2 + kkey * LDK + kdc + 4 * i) = u;
            }
            const float r0v[8] = {va0.x,va0.y,va0.z,va0.w,va1.x,va1.y,va1.z,va1.w};
            const float r1v[8] = {vb0.x,vb0.y,vb0.z,vb0.w,vb1.x,vb1.y,vb1.z,vb1.w};
#pragma unroll
            for (int i = 0; i < 8; i++)
                *(__half2*)(Vs2 + (vd0 + i) * LDVH + vkgbase + vpb) =
                    __floats2half2_rn(r0v[i], r1v[i]);
        }
        __syncthreads();
    }

    // ---- epilogue: normalize + store ----
    const float inv0 = 1.f / lrow0;
    const float inv1 = 1.f / lrow1;
#pragma unroll
    for (int nd = 0; nd < 8; nd++) {
        const int dcol = 8 * nd + 2 * c;
        float2 w0 = make_float2(o[nd][0] * inv0, o[nd][1] * inv0);
        float2 w1 = make_float2(o[nd][2] * inv1, o[nd][3] * inv1);
        *(float2*)(Og + (size_t)rowA * Dn + dcol) = w0;
        *(float2*)(Og + (size_t)rowB * Dn + dcol) = w1;
    }
}

extern "C" void kernel_launch(void* const* d_in, const int* in_sizes, int n_in,
                              void* d_out, int out_size)
{
    const float* Q = (const float*)d_in[0];
    const float* K = (const float*)d_in[1];
    const float* V = (const float*)d_in[2];
    const void*  M = (const void*)d_in[3];
    float* O = (float*)d_out;

    cudaFuncSetAttribute(attn_mma_kernel,
                         cudaFuncAttributeMaxDynamicSharedMemorySize, SMEM_BYTES);

    probe_mask_kernel<<<1, 256>>>((const unsigned int*)M);

    dim3 grid(Sn / BM, Bn * Hn);   // (16, 32)
    attn_mma_kernel<<<grid, NTHR, SMEM_BYTES>>>(Q, K, V, M, O);
}